// round 16
// baseline (speedup 1.0000x reference)
#include <cuda_runtime.h>
#include <cuda_fp16.h>
#include <cstdint>

#define SEQ   2048
#define EMB   1024
#define NH    16
#define HD    64
#define BATCH 2
#define MTOT  (BATCH*SEQ)     // 4096
#define BHTOT (BATCH*NH)      // 32

// ---------------- scratch (static device globals; no allocations) ----------
__device__ __half g_Xhi[MTOT*EMB],  g_Xlo[MTOT*EMB];
__device__ __half g_Wqhi[EMB*EMB],  g_Wqlo[EMB*EMB];
__device__ __half g_Wkhi[EMB*EMB],  g_Wklo[EMB*EMB];
__device__ __half g_Wvhi[EMB*EMB];                      // V proj: 1-pass
__device__ __half g_Wohi[EMB*EMB];                      // out proj: 1-pass
__device__ __half g_Hc[MTOT*EMB];                       // single fp16

// Attention operands (fp16 hi/lo for BOTH Q and K — softmax path needs it).
// Q has x8 logit scale folded (exact).
__device__ __half g_Qhi[BHTOT*SEQ*HD], g_Qlo[BHTOT*SEQ*HD];
__device__ __half g_Khi[BHTOT*SEQ*HD], g_Klo[BHTOT*SEQ*HD];
// V stored transposed, single fp16: [bh][d][seq]
__device__ __half g_Vt[BHTOT*HD*SEQ];

// ---------------- PTX helpers ----------------------------------------------
__device__ __forceinline__ uint32_t smem_u32(const void* p) {
    uint32_t a;
    asm("{ .reg .u64 t; cvta.to.shared.u64 t, %1; cvt.u32.u64 %0, t; }"
        : "=r"(a) : "l"(p));
    return a;
}
__device__ __forceinline__ void cp16(uint32_t sdst, const void* gsrc) {
    asm volatile("cp.async.cg.shared.global [%0], [%1], 16;"
                 :: "r"(sdst), "l"(gsrc));
}
__device__ __forceinline__ void ldsm_x4(uint32_t a[4], uint32_t addr) {
    asm volatile("ldmatrix.sync.aligned.m8n8.x4.shared.b16 {%0,%1,%2,%3}, [%4];"
                 : "=r"(a[0]), "=r"(a[1]), "=r"(a[2]), "=r"(a[3]) : "r"(addr));
}
__device__ __forceinline__ void mma16816(float d[4], const uint32_t a[4],
                                         const uint32_t b[2]) {
    asm volatile(
        "mma.sync.aligned.m16n8k16.row.col.f32.f16.f16.f32 "
        "{%0,%1,%2,%3}, {%4,%5,%6,%7}, {%8,%9}, {%0,%1,%2,%3};"
        : "+f"(d[0]), "+f"(d[1]), "+f"(d[2]), "+f"(d[3])
        : "r"(a[0]), "r"(a[1]), "r"(a[2]), "r"(a[3]), "r"(b[0]), "r"(b[1]));
}
__device__ __forceinline__ uint32_t pack_h2(float a, float b) {
    __half2 t = __floats2half2_rn(a, b);
    return *(uint32_t*)&t;
}

// ---------------- mma.sync GEMM (128x128) ----------------------------------
// PASSES=3: acc += Ah*Bh + Ah*Bl + Al*Bh   (2 stages, 40KB/stage)
// PASSES=1: acc += Ah*Bh                   (4 stages, 20KB/stage)
// Compact per-PASSES stage layout (no holes).
#define BK 32
#define NCHUNK (EMB/BK)       // 32
#define STRB 80               // smem row stride bytes (32 fp16 + 8 pad)
#define GEMM_SMEM_BYTES 81920 // 80 KB either way

template<int PASSES> struct GCfg {
    static constexpr uint32_t AHI = 0;
    static constexpr uint32_t ALO = 10240;                       // PASSES>=2
    static constexpr uint32_t BHI = (PASSES >= 2) ? 20480 : 10240;
    static constexpr uint32_t BLO = 30720;                       // PASSES==3
    static constexpr uint32_t STG =
        (PASSES == 3) ? 40960u : ((PASSES == 2) ? 30720u : 20480u);
    static constexpr int NSTAGES = (PASSES == 3) ? 2 : 4;
};

template<int PASSES>
__device__ __forceinline__ void gemm_load_chunk(
    uint32_t sb, int stage, int kc, int bm, int bn,
    const __half* __restrict__ Ahi, const __half* __restrict__ Alo,
    const __half* __restrict__ Bhi, const __half* __restrict__ Blo,
    int tid)
{
    using C = GCfg<PASSES>;
    const uint32_t st = sb + (uint32_t)stage * C::STG;
#pragma unroll
    for (int i = 0; i < 2; i++) {
        int idx = tid + i * 256;
        int row = idx >> 2, ch = idx & 3;
        uint32_t so = (uint32_t)(row * STRB + ch * 16);
        size_t ga = (size_t)(bm + row) * EMB + kc * BK + ch * 8;
        size_t gb = (size_t)(bn + row) * EMB + kc * BK + ch * 8;
        cp16(st + C::AHI + so, Ahi + ga);
        if (PASSES >= 2) cp16(st + C::ALO + so, Alo + ga);
        cp16(st + C::BHI + so, Bhi + gb);
        if (PASSES == 3) cp16(st + C::BLO + so, Blo + gb);
    }
    asm volatile("cp.async.commit_group;" ::: "memory");
}

template<int PASSES>
__device__ __forceinline__ void gemm_compute_stage(
    uint32_t sbase, int wm, int wn, int lane, float acc[4][4][4])
{
    using C = GCfg<PASSES>;
    const int ra      = lane & 15;
    const uint32_t ka = (uint32_t)((lane >> 4) * 16);
    const int rb      = ((lane >> 4) << 3) + (lane & 7);
    const uint32_t kb = (uint32_t)(((lane >> 3) & 1) * 16);
#pragma unroll
    for (int ks = 0; ks < 2; ks++) {
        uint32_t ah[4][4], al[4][4], bh[2][4], bl[2][4];
#pragma unroll
        for (int mi = 0; mi < 4; mi++) {
            uint32_t r = sbase + (uint32_t)((wm*64 + mi*16 + ra) * STRB) + ks*32 + ka;
            ldsm_x4(ah[mi], r + C::AHI);
            if (PASSES >= 2) ldsm_x4(al[mi], r + C::ALO);
        }
#pragma unroll
        for (int nj = 0; nj < 2; nj++) {
            uint32_t r = sbase + (uint32_t)((wn*32 + nj*16 + rb) * STRB) + ks*32 + kb;
            ldsm_x4(bh[nj], r + C::BHI);
            if (PASSES == 3) ldsm_x4(bl[nj], r + C::BLO);
        }
#pragma unroll
        for (int mi = 0; mi < 4; mi++)
#pragma unroll
            for (int nj = 0; nj < 2; nj++) {
                mma16816(acc[mi][2*nj],   ah[mi], bh[nj]);
                mma16816(acc[mi][2*nj+1], ah[mi], bh[nj] + 2);
            }
        if (PASSES == 3) {
#pragma unroll
            for (int mi = 0; mi < 4; mi++)
#pragma unroll
                for (int nj = 0; nj < 2; nj++) {
                    mma16816(acc[mi][2*nj],   ah[mi], bl[nj]);
                    mma16816(acc[mi][2*nj+1], ah[mi], bl[nj] + 2);
                }
        }
        if (PASSES >= 2) {
#pragma unroll
            for (int mi = 0; mi < 4; mi++)
#pragma unroll
                for (int nj = 0; nj < 2; nj++) {
                    mma16816(acc[mi][2*nj],   al[mi], bh[nj]);
                    mma16816(acc[mi][2*nj+1], al[mi], bh[nj] + 2);
                }
        }
    }
}

// Multi-stage single-sync pipeline:
// prologue issues STAGES-1 loads; iter c: wait(STAGES-2) -> sync ->
// load(c+STAGES-1) -> compute(c). The sync orders stage reuse.
template<int PASSES>
__device__ __forceinline__ void gemm_mainloop(
    uint32_t sb, int bm, int bn,
    const __half* Ahi, const __half* Alo,
    const __half* Bhi, const __half* Blo,
    int tid, int wm, int wn, int lane, float acc[4][4][4])
{
    using C = GCfg<PASSES>;
    constexpr int NS = C::NSTAGES;
#pragma unroll
    for (int mi = 0; mi < 4; mi++)
#pragma unroll
        for (int ni = 0; ni < 4; ni++)
#pragma unroll
            for (int q = 0; q < 4; q++) acc[mi][ni][q] = 0.f;

#pragma unroll
    for (int p = 0; p < NS - 1; p++)
        gemm_load_chunk<PASSES>(sb, p, p, bm, bn, Ahi, Alo, Bhi, Blo, tid);

    int cs = 0;   // compute stage
    int ls = NS - 1;  // next load stage
    for (int c = 0; c < NCHUNK; c++) {
        asm volatile("cp.async.wait_group %0;" :: "n"(NS - 2) : "memory");
        __syncthreads();
        if (c + NS - 1 < NCHUNK) {
            gemm_load_chunk<PASSES>(sb, ls, c + NS - 1, bm, bn,
                                    Ahi, Alo, Bhi, Blo, tid);
            if (++ls == NS) ls = 0;
        }
        gemm_compute_stage<PASSES>(sb + (uint32_t)(cs * C::STG), wm, wn, lane, acc);
        if (++cs == NS) cs = 0;
    }
}

// ---------------- split kernel: fp32 -> (fp16 hi [, fp16 lo]) --------------
__global__ __launch_bounds__(256) void split_kernel(
    const float* __restrict__ x,
    const float* __restrict__ Wq, const float* __restrict__ Wk,
    const float* __restrict__ Wv, const float* __restrict__ Wo)
{
    const float* src; __half* hi; __half* lo; int n4; bool wlo;
    switch (blockIdx.z) {
        case 0:  src = x;  hi = g_Xhi;  lo = g_Xlo;  n4 = MTOT*EMB/4; wlo = true;  break;
        case 1:  src = Wq; hi = g_Wqhi; lo = g_Wqlo; n4 = EMB*EMB/4;  wlo = true;  break;
        case 2:  src = Wk; hi = g_Wkhi; lo = g_Wklo; n4 = EMB*EMB/4;  wlo = true;  break;
        case 3:  src = Wv; hi = g_Wvhi; lo = nullptr; n4 = EMB*EMB/4; wlo = false; break;
        default: src = Wo; hi = g_Wohi; lo = nullptr; n4 = EMB*EMB/4; wlo = false; break;
    }
    for (int i = blockIdx.x * blockDim.x + threadIdx.x; i < n4;
         i += gridDim.x * blockDim.x) {
        float4 v = ((const float4*)src)[i];
        __half h0 = __float2half_rn(v.x);
        __half h1 = __float2half_rn(v.y);
        __half h2 = __float2half_rn(v.z);
        __half h3 = __float2half_rn(v.w);
        ((__half2*)hi)[2*i]   = __halves2half2(h0, h1);
        ((__half2*)hi)[2*i+1] = __halves2half2(h2, h3);
        if (wlo) {
            __half l0 = __float2half_rn(v.x - __half2float(h0));
            __half l1 = __float2half_rn(v.y - __half2float(h1));
            __half l2 = __float2half_rn(v.z - __half2float(h2));
            __half l3 = __float2half_rn(v.w - __half2float(h3));
            ((__half2*)lo)[2*i]   = __halves2half2(l0, l1);
            ((__half2*)lo)[2*i+1] = __halves2half2(l2, l3);
        }
    }
}

// ---------------- QKV projection: GEMM + epilogue ---------------------------
__global__ __launch_bounds__(256) void qkv_gemm_tc(
    const float* __restrict__ bq, const float* __restrict__ bk,
    const float* __restrict__ bv)
{
    extern __shared__ char dsm[];
    uint32_t sb = smem_u32(dsm);
    const int tid = threadIdx.x, wid = tid >> 5, lane = tid & 31;
    const int wm = wid >> 2, wn = wid & 3;
    const int bm = blockIdx.x * 128, bn = blockIdx.y * 128;
    const int z = blockIdx.z;

    float acc[4][4][4];
    const float* bias;
    if (z == 0) {
        bias = bq;
        gemm_mainloop<3>(sb, bm, bn, g_Xhi, g_Xlo, g_Wqhi, g_Wqlo,
                         tid, wm, wn, lane, acc);
    } else if (z == 1) {
        bias = bk;
        gemm_mainloop<3>(sb, bm, bn, g_Xhi, g_Xlo, g_Wkhi, g_Wklo,
                         tid, wm, wn, lane, acc);
    } else {
        bias = bv;
        gemm_mainloop<1>(sb, bm, bn, g_Xhi, nullptr, g_Wvhi, nullptr,
                         tid, wm, wn, lane, acc);
    }

    const int g = lane >> 2, tg = lane & 3;
    const float scl = (z == 0) ? 8.0f : 1.0f;
#pragma unroll
    for (int ni = 0; ni < 4; ni++) {
        const int c0 = bn + wn*32 + ni*8 + 2*tg;
        const float bx = bias[c0], by = bias[c0 + 1];
        const int h  = c0 >> 6;
        const int d0 = c0 & 63;
#pragma unroll
        for (int mi = 0; mi < 4; mi++) {
#pragma unroll
            for (int half = 0; half < 2; half++) {
                const int r = bm + wm*64 + mi*16 + g + half*8;
                const int b = r >> 11;
                const int n = r & (SEQ - 1);
                const int bh = (b << 4) + h;
                float v0 = (acc[mi][ni][half*2 + 0] + bx) * scl;
                float v1 = (acc[mi][ni][half*2 + 1] + by) * scl;
                if (z == 2) {
                    // V transposed single fp16: [bh][d][seq]
                    size_t o0 = ((size_t)bh * HD + d0) * SEQ + n;
                    g_Vt[o0]       = __float2half_rn(v0);
                    g_Vt[o0 + SEQ] = __float2half_rn(v1);
                } else {
                    __half h0 = __float2half_rn(v0);
                    __half h1 = __float2half_rn(v1);
                    __half l0 = __float2half_rn(v0 - __half2float(h0));
                    __half l1 = __float2half_rn(v1 - __half2float(h1));
                    size_t o = ((size_t)bh * SEQ + n) * HD + d0;
                    if (z == 0) {
                        *(__half2*)(g_Qhi + o) = __halves2half2(h0, h1);
                        *(__half2*)(g_Qlo + o) = __halves2half2(l0, l1);
                    } else {
                        *(__half2*)(g_Khi + o) = __halves2half2(h0, h1);
                        *(__half2*)(g_Klo + o) = __halves2half2(l0, l1);
                    }
                }
            }
        }
    }
}

// ---------------- output projection (1-pass, 4-stage) ------------------------
__global__ __launch_bounds__(256) void out_gemm_tc(
    const float* __restrict__ bo, float* __restrict__ outp)
{
    extern __shared__ char dsm[];
    uint32_t sb = smem_u32(dsm);
    const int tid = threadIdx.x, wid = tid >> 5, lane = tid & 31;
    const int wm = wid >> 2, wn = wid & 3;
    const int bm = blockIdx.x * 128, bn = blockIdx.y * 128;

    float acc[4][4][4];
    gemm_mainloop<1>(sb, bm, bn, g_Hc, nullptr, g_Wohi, nullptr,
                     tid, wm, wn, lane, acc);

    const int g = lane >> 2, tg = lane & 3;
#pragma unroll
    for (int ni = 0; ni < 4; ni++) {
        const int c0 = bn + wn*32 + ni*8 + 2*tg;
        const float bx = bo[c0], by = bo[c0 + 1];
#pragma unroll
        for (int mi = 0; mi < 4; mi++) {
#pragma unroll
            for (int half = 0; half < 2; half++) {
                const int r = bm + wm*64 + mi*16 + g + half*8;
                float* op = outp + (size_t)r * EMB + c0;
                float2 v = make_float2(acc[mi][ni][half*2 + 0] + bx,
                                       acc[mi][ni][half*2 + 1] + by);
                *(float2*)op = v;
            }
        }
    }
}

// ---------------- flash attention on HMMA, 3-stage KV pipeline ---------------
// S = QK^T: 3-pass fp16 (Qh*Kh + Ql*Kh + Qh*Kl).  PV: 1-pass.
#define ASTR 144                      // 64 fp16 + 8 pad = 144 B rows
#define AKHI 0
#define AKLO 9216
#define AVS  18432
#define ASTG 27648                    // bytes per stage
#define ANST 3                        // stages
#define ATT_SMEM (ANST*ASTG)          // 81 KB
#define NKT (SEQ/64)                  // 32

__device__ __forceinline__ void att_load_kv(uint32_t sb, int stage, int kt,
                                            int bh, int tid)
{
    const uint32_t st = sb + (uint32_t)stage * ASTG;
    const __half* kh = g_Khi + ((size_t)bh*SEQ + kt*64) * HD;
    const __half* kl = g_Klo + ((size_t)bh*SEQ + kt*64) * HD;
    const __half* vt = g_Vt  + (size_t)bh*HD*SEQ + kt*64;
#pragma unroll
    for (int i = 0; i < 2; i++) {
        int idx = tid + i * 256;
        int row = idx >> 3, ch = idx & 7;
        uint32_t so = (uint32_t)(row * ASTR + ch * 16);
        cp16(st + AKHI + so, kh + (size_t)row * HD + ch * 8);
        cp16(st + AKLO + so, kl + (size_t)row * HD + ch * 8);
        cp16(st + AVS  + so, vt + (size_t)row * SEQ + ch * 8);
    }
    asm volatile("cp.async.commit_group;" ::: "memory");
}

__global__ __launch_bounds__(256, 2) void attn_mma()
{
    extern __shared__ char dsm[];
    uint32_t sb = smem_u32(dsm);
    const int tid = threadIdx.x, wid = tid >> 5, lane = tid & 31;
    const int g = lane >> 2, tg = lane & 3;
    const int bh = blockIdx.y, qblk = blockIdx.x;

    // ---- stage Q (hi at sb, lo at sb+18432), capture A-frags ----
    {
        const __half* qh = g_Qhi + ((size_t)bh*SEQ + qblk*128) * HD;
        const __half* ql = g_Qlo + ((size_t)bh*SEQ + qblk*128) * HD;
#pragma unroll
        for (int i = 0; i < 4; i++) {
            int idx = tid + i * 256;
            int row = idx >> 3, ch = idx & 7;
            uint32_t so = (uint32_t)(row * ASTR + ch * 16);
            cp16(sb + so,         qh + (size_t)row * HD + ch * 8);
            cp16(sb + 18432 + so, ql + (size_t)row * HD + ch * 8);
        }
        asm volatile("cp.async.commit_group;" ::: "memory");
        asm volatile("cp.async.wait_group 0;" ::: "memory");
        __syncthreads();
    }
    uint32_t qh[4][4], ql[4][4];
    {
        uint32_t qa = sb + (uint32_t)((wid*16 + (lane & 15)) * ASTR)
                         + (uint32_t)((lane >> 4) * 16);
#pragma unroll
        for (int ks = 0; ks < 4; ks++) {
            ldsm_x4(qh[ks], qa + ks*32);
            ldsm_x4(ql[ks], qa + 18432 + ks*32);
        }
    }
    __syncthreads();   // Q smem free for KV stages

    float oacc[8][4];
#pragma unroll
    for (int nf = 0; nf < 8; nf++)
#pragma unroll
        for (int q = 0; q < 4; q++) oacc[nf][q] = 0.f;
    float m_a = -1e30f, m_b = -1e30f, l_a = 0.f, l_b = 0.f;

    // x4 B-fragment addressing: 16-row groups.
    const int rb      = ((lane >> 4) << 3) + (lane & 7);
    const uint32_t kb = (uint32_t)(((lane >> 3) & 1) * 16);

    att_load_kv(sb, 0, 0, bh, tid);
    att_load_kv(sb, 1, 1, bh, tid);

    int cs = 0, ls = 2;
    for (int t = 0; t < NKT; t++) {
        asm volatile("cp.async.wait_group 1;" ::: "memory");
        __syncthreads();
        if (t + 2 < NKT) {
            att_load_kv(sb, ls, t + 2, bh, tid);
            if (++ls == ANST) ls = 0;
        }
        const uint32_t st = sb + (uint32_t)(cs * ASTG);
        if (++cs == ANST) cs = 0;

        // ---- S = Q K^T (3-pass fp16; x4 K fragments) ----
        float sacc[8][4];
#pragma unroll
        for (int nf = 0; nf < 8; nf++)
#pragma unroll
            for (int q = 0; q < 4; q++) sacc[nf][q] = 0.f;

#pragma unroll
        for (int ks = 0; ks < 4; ks++) {
#pragma unroll
            for (int np = 0; np < 4; np++) {
                const int nf0 = 2*np, nf1 = 2*np + 1;
                uint32_t ka = st + (uint32_t)((np*16 + rb) * ASTR) + kb + ks*32;
                uint32_t kh4[4], kl4[4];
                ldsm_x4(kh4, ka + AKHI);
                ldsm_x4(kl4, ka + AKLO);
                mma16816(sacc[nf0], qh[ks], kh4);
                mma16816(sacc[nf1], qh[ks], kh4 + 2);
                mma16816(sacc[nf0], ql[ks], kh4);
                mma16816(sacc[nf1], ql[ks], kh4 + 2);
                mma16816(sacc[nf0], qh[ks], kl4);
                mma16816(sacc[nf1], qh[ks], kl4 + 2);
            }
        }

        // ---- online softmax (rows g and g+8; reduce over tg lanes) ----
        float mx_a = sacc[0][0], mx_b = sacc[0][2];
#pragma unroll
        for (int nf = 0; nf < 8; nf++) {
            mx_a = fmaxf(mx_a, fmaxf(sacc[nf][0], sacc[nf][1]));
            mx_b = fmaxf(mx_b, fmaxf(sacc[nf][2], sacc[nf][3]));
        }
        mx_a = fmaxf(mx_a, __shfl_xor_sync(0xffffffffu, mx_a, 1));
        mx_a = fmaxf(mx_a, __shfl_xor_sync(0xffffffffu, mx_a, 2));
        mx_b = fmaxf(mx_b, __shfl_xor_sync(0xffffffffu, mx_b, 1));
        mx_b = fmaxf(mx_b, __shfl_xor_sync(0xffffffffu, mx_b, 2));

        float mna = fmaxf(m_a, mx_a), mnb = fmaxf(m_b, mx_b);
        float ala = __expf(m_a - mna), alb = __expf(m_b - mnb);
        m_a = mna; m_b = mnb;

        // exp -> fp16 P A-fragments; l sums the ROUNDED values for consistency.
        uint32_t phi[4][4];
        float rs_a = 0.f, rs_b = 0.f;
#pragma unroll
        for (int ks = 0; ks < 4; ks++) {
#pragma unroll
            for (int jj = 0; jj < 2; jj++) {
                const int nf = 2*ks + jj;
                float p0 = __expf(sacc[nf][0] - m_a);
                float p1 = __expf(sacc[nf][1] - m_a);
                float p2 = __expf(sacc[nf][2] - m_b);
                float p3 = __expf(sacc[nf][3] - m_b);
                float h0f = __half2float(__float2half_rn(p0));
                float h1f = __half2float(__float2half_rn(p1));
                float h2f = __half2float(__float2half_rn(p2));
                float h3f = __half2float(__float2half_rn(p3));
                rs_a += h0f + h1f;
                rs_b += h2f + h3f;
                phi[ks][2*jj + 0] = pack_h2(h0f, h1f);
                phi[ks][2*jj + 1] = pack_h2(h2f, h3f);
            }
        }
        rs_a += __shfl_xor_sync(0xffffffffu, rs_a, 1);
        rs_a += __shfl_xor_sync(0xffffffffu, rs_a, 2);
        rs_b += __shfl_xor_sync(0xffffffffu, rs_b, 1);
        rs_b += __shfl_xor_sync(0xffffffffu, rs_b, 2);
        l_a = l_a * ala + rs_a;
        l_b = l_b * alb + rs_b;
#pragma unroll
        for (int nf = 0; nf < 8; nf++) {
            oacc[nf][0] *= ala; oacc[nf][1] *= ala;
            oacc[nf][2] *= alb; oacc[nf][3] *= alb;
        }

        // ---- O += P V (1-pass; x4 V fragments) ----
#pragma unroll
        for (int ks = 0; ks < 4; ks++) {
#pragma unroll
            for (int np = 0; np < 4; np++) {
                const int nf0 = 2*np, nf1 = 2*np + 1;
                uint32_t va = st + (uint32_t)((np*16 + rb) * ASTR) + kb + ks*32;
                uint32_t v4[4];
                ldsm_x4(v4, va + AVS);
                mma16816(oacc[nf0], phi[ks], v4);
                mma16816(oacc[nf1], phi[ks], v4 + 2);
            }
        }
    }

    // ---- epilogue: normalize, emit Hc single fp16 ----
    const float iva = 1.0f / l_a, ivb = 1.0f / l_b;
    const int b = bh >> 4, h = bh & 15;
    const int tok_a = qblk*128 + wid*16 + g;
    const int tok_b = tok_a + 8;
#pragma unroll
    for (int nf = 0; nf < 8; nf++) {
        const int d = h*HD + nf*8 + 2*tg;
        float v0 = oacc[nf][0]*iva, v1 = oacc[nf][1]*iva;
        float v2 = oacc[nf][2]*ivb, v3 = oacc[nf][3]*ivb;
        size_t oa = ((size_t)(b*SEQ + tok_a))*EMB + d;
        size_t ob = ((size_t)(b*SEQ + tok_b))*EMB + d;
        *(__half2*)(g_Hc + oa) =
            __halves2half2(__float2half_rn(v0), __float2half_rn(v1));
        *(__half2*)(g_Hc + ob) =
            __halves2half2(__float2half_rn(v2), __float2half_rn(v3));
    }
}

// ---------------------------------------------------------------------------
extern "C" void kernel_launch(void* const* d_in, const int* in_sizes, int n_in,
                              void* d_out, int out_size)
{
    (void)in_sizes; (void)n_in; (void)out_size;
    const float* x  = (const float*)d_in[0];
    const float* Wq = (const float*)d_in[1];
    const float* bq = (const float*)d_in[2];
    const float* Wk = (const float*)d_in[3];
    const float* bk = (const float*)d_in[4];
    const float* Wv = (const float*)d_in[5];
    const float* bv = (const float*)d_in[6];
    const float* Wo = (const float*)d_in[7];
    const float* bo = (const float*)d_in[8];
    float* out = (float*)d_out;

    cudaFuncSetAttribute(qkv_gemm_tc,
                         cudaFuncAttributeMaxDynamicSharedMemorySize,
                         GEMM_SMEM_BYTES);
    cudaFuncSetAttribute(out_gemm_tc,
                         cudaFuncAttributeMaxDynamicSharedMemorySize,
                         GEMM_SMEM_BYTES);
    cudaFuncSetAttribute(attn_mma,
                         cudaFuncAttributeMaxDynamicSharedMemorySize,
                         ATT_SMEM);

    split_kernel<<<dim3(128, 1, 5), 256>>>(x, Wq, Wk, Wv, Wo);
    qkv_gemm_tc<<<dim3(MTOT/128, EMB/128, 3), 256, GEMM_SMEM_BYTES>>>(bq, bk, bv);
    attn_mma<<<dim3(SEQ/128, BHTOT), 256, ATT_SMEM>>>();
    out_gemm_tc<<<dim3(MTOT/128, EMB/128), 256, GEMM_SMEM_BYTES>>>(bo, out);
}